// round 11
// baseline (speedup 1.0000x reference)
#include <cuda_runtime.h>
#include <math.h>
#include <stdint.h>

#define N_SAMP 1024
#define D      16384
#define WH     128
#define SA     132   // attn smem stride (words); 132%4==0 -> 16B rows; 132%32=4 -> conflict-free phases
#define GSA    18    // gram stage row stride (words)

typedef unsigned long long ull;

// ---- device scratch (no allocations allowed) ----
__device__ float g_gram[N_SAMP * N_SAMP];
__device__ float g_part[144 * 16384];      // split-K partial tiles
__device__ float g_sq[N_SAMP];
__device__ int   g_hp[N_SAMP];
__device__ int   g_hn[N_SAMP];
__device__ float g_dd[2 * N_SAMP];

// ---- packed fp32x2 FMA (Blackwell dual fp32; exact fp32 math) ----
__device__ __forceinline__ void ffma2(ull& d, ull a, ull b) {
    asm("fma.rn.f32x2 %0, %1, %2, %0;" : "+l"(d) : "l"(a), "l"(b));
}
__device__ __forceinline__ float f2sum(ull v) {
    return __uint_as_float((unsigned)(v & 0xFFFFFFFFu)) +
           __uint_as_float((unsigned)(v >> 32));
}

// ===========================================================================
// Kernel 2: Gram GEMM with FFMA2 (unchanged: at its FFMA2 floor).
// 36 triangular 128x128 tiles x 4 K-splits = 144 blocks (one wave).
// ===========================================================================
__global__ __launch_bounds__(256, 1)
void gram_f2(const float* __restrict__ X) {
    __shared__ __align__(16) float As[2][128 * GSA];
    __shared__ __align__(16) float Bs[2][128 * GSA];

    const int tid = threadIdx.x;
    const int tx  = tid & 15;
    const int ty  = tid >> 4;

    int blk = blockIdx.x;
    int split = blk / 36;
    int tile  = blk % 36;
    int r = tile, bi = 0;
    while (r >= 8 - bi) { r -= 8 - bi; bi++; }
    int bj = bi + r;

    const float* Ag = X + (size_t)(bi * 128) * D + split * 4096;
    const float* Bg = X + (size_t)(bj * 128) * D + split * 4096;

    const int lr0 = tid >> 2;
    const int lr1 = lr0 + 64;
    const int lc  = (tid & 3) << 2;

    ull acc[8][8];
#pragma unroll
    for (int m = 0; m < 8; m++)
#pragma unroll
        for (int n = 0; n < 8; n++) acc[m][n] = 0ull;

    float4 pa0 = *(const float4*)(Ag + (size_t)lr0 * D + lc);
    float4 pa1 = *(const float4*)(Ag + (size_t)lr1 * D + lc);
    float4 pb0 = *(const float4*)(Bg + (size_t)lr0 * D + lc);
    float4 pb1 = *(const float4*)(Bg + (size_t)lr1 * D + lc);
    *(float2*)&As[0][lr0 * GSA + lc]     = make_float2(pa0.x, pa0.y);
    *(float2*)&As[0][lr0 * GSA + lc + 2] = make_float2(pa0.z, pa0.w);
    *(float2*)&As[0][lr1 * GSA + lc]     = make_float2(pa1.x, pa1.y);
    *(float2*)&As[0][lr1 * GSA + lc + 2] = make_float2(pa1.z, pa1.w);
    *(float2*)&Bs[0][lr0 * GSA + lc]     = make_float2(pb0.x, pb0.y);
    *(float2*)&Bs[0][lr0 * GSA + lc + 2] = make_float2(pb0.z, pb0.w);
    *(float2*)&Bs[0][lr1 * GSA + lc]     = make_float2(pb1.x, pb1.y);
    *(float2*)&Bs[0][lr1 * GSA + lc + 2] = make_float2(pb1.z, pb1.w);
    __syncthreads();

    const int NC = 4096 / 16;
    int cur = 0;
    for (int c = 0; c < NC; c++) {
        bool more = (c + 1) < NC;
        if (more) {
            int kk = (c + 1) * 16;
            pa0 = *(const float4*)(Ag + (size_t)lr0 * D + kk + lc);
            pa1 = *(const float4*)(Ag + (size_t)lr1 * D + kk + lc);
            pb0 = *(const float4*)(Bg + (size_t)lr0 * D + kk + lc);
            pb1 = *(const float4*)(Bg + (size_t)lr1 * D + kk + lc);
        }
#pragma unroll
        for (int kp = 0; kp < 8; kp++) {
            ull av[8], bv[8];
#pragma unroll
            for (int m = 0; m < 8; m++)
                av[m] = *(const ull*)&As[cur][(ty + 16 * m) * GSA + 2 * kp];
#pragma unroll
            for (int n = 0; n < 8; n++)
                bv[n] = *(const ull*)&Bs[cur][(tx + 16 * n) * GSA + 2 * kp];
#pragma unroll
            for (int m = 0; m < 8; m++)
#pragma unroll
                for (int n = 0; n < 8; n++) ffma2(acc[m][n], av[m], bv[n]);
        }
        if (more) {
            int nxt = cur ^ 1;
            *(float2*)&As[nxt][lr0 * GSA + lc]     = make_float2(pa0.x, pa0.y);
            *(float2*)&As[nxt][lr0 * GSA + lc + 2] = make_float2(pa0.z, pa0.w);
            *(float2*)&As[nxt][lr1 * GSA + lc]     = make_float2(pa1.x, pa1.y);
            *(float2*)&As[nxt][lr1 * GSA + lc + 2] = make_float2(pa1.z, pa1.w);
            *(float2*)&Bs[nxt][lr0 * GSA + lc]     = make_float2(pb0.x, pb0.y);
            *(float2*)&Bs[nxt][lr0 * GSA + lc + 2] = make_float2(pb0.z, pb0.w);
            *(float2*)&Bs[nxt][lr1 * GSA + lc]     = make_float2(pb1.x, pb1.y);
            *(float2*)&Bs[nxt][lr1 * GSA + lc + 2] = make_float2(pb1.z, pb1.w);
            __syncthreads();
            cur = nxt;
        }
    }

    float* dst = g_part + (size_t)blk * 16384;
#pragma unroll
    for (int m = 0; m < 8; m++)
#pragma unroll
        for (int n = 0; n < 8; n++)
            dst[(ty + 16 * m) * 128 + (tx + 16 * n)] = f2sum(acc[m][n]);
}

// ===========================================================================
// Kernel 2b: reduce split-K partials, write G, mirror, and diagonal -> g_sq
// ===========================================================================
__global__ void gram_reduce() {
    int tile = blockIdx.x;
    int r = tile, bi = 0;
    while (r >= 8 - bi) { r -= 8 - bi; bi++; }
    int bj = bi + r;
    const float* p0 = g_part + (size_t)(0 * 36 + tile) * 16384;
    const float* p1 = g_part + (size_t)(1 * 36 + tile) * 16384;
    const float* p2 = g_part + (size_t)(2 * 36 + tile) * 16384;
    const float* p3 = g_part + (size_t)(3 * 36 + tile) * 16384;
    for (int u = threadIdx.x; u < 16384; u += 256) {
        float s = p0[u] + p1[u] + p2[u] + p3[u];
        int rr = u >> 7, cc = u & 127;
        int i = bi * 128 + rr, j = bj * 128 + cc;
        g_gram[i * N_SAMP + j] = s;
        if (bi != bj) g_gram[j * N_SAMP + i] = s;
        else if (rr == cc) g_sq[i] = s;   // diagonal = squared norm
    }
}

// ===========================================================================
// Kernel 3: hard mining
// ===========================================================================
__global__ void mine_kernel(const int* __restrict__ targets) {
    int i   = blockIdx.x;
    int tid = threadIdx.x;
    int tg  = targets[i];

    float bpv = -3.0e38f; int bpi = 0;
    float bnv =  3.0e38f; int bni = 0;
    for (int j = tid; j < N_SAMP; j += 256) {
        float val = g_sq[j] - 2.f * g_gram[i * N_SAMP + j];
        if (targets[j] == tg) {
            if (val > bpv || (val == bpv && j < bpi)) { bpv = val; bpi = j; }
        } else {
            if (val < bnv || (val == bnv && j < bni)) { bnv = val; bni = j; }
        }
    }
    __shared__ float spv[256]; __shared__ int spi[256];
    __shared__ float snv[256]; __shared__ int sni[256];
    spv[tid] = bpv; spi[tid] = bpi; snv[tid] = bnv; sni[tid] = bni;
    __syncthreads();
    for (int st = 128; st > 0; st >>= 1) {
        if (tid < st) {
            float ov = spv[tid + st]; int oi = spi[tid + st];
            if (ov > spv[tid] || (ov == spv[tid] && oi < spi[tid])) { spv[tid] = ov; spi[tid] = oi; }
            float nv = snv[tid + st]; int ni2 = sni[tid + st];
            if (nv < snv[tid] || (nv == snv[tid] && ni2 < sni[tid])) { snv[tid] = nv; sni[tid] = ni2; }
        }
        __syncthreads();
    }
    if (tid == 0) { g_hp[i] = spi[0]; g_hn[i] = sni[0]; }
}

// ===========================================================================
// Kernel 4: attention + distance. 512 threads, 4x8 microtile, k-quad LDS.128
// operands (ulonglong2) -> half the LDS instructions of R8. Register softmax,
// fused distance epilogue. b1 = A natural -> P natural; b2 = O natural -> O^T.
// ===========================================================================
__global__ __launch_bounds__(512, 1)
void attn_kernel(const float* __restrict__ X) {
    extern __shared__ __align__(16) float sm[];
    float* b1 = sm;              // A natural -> P natural
    float* b2 = sm + 128 * SA;   // O natural -> O^T
    __shared__ float xch[512];

    const int tid = threadIdx.x;
    const int tx  = tid & 15;       // j/c index: tx + 16n, n<8
    const int ty  = tid >> 4;       // i index:   ty + 32m, m<4
    const int blk = blockIdx.x;
    const int bb  = blk >> 1;
    const int oidx = (blk & 1) ? g_hn[bb] : g_hp[bb];
    const float* Ag = X + (size_t)bb * D;
    const float* Og = X + (size_t)oidx * D;

    // ---- phase 1: A natural -> b1, O natural -> b2 (float4, rows 16B-aligned) ----
    for (int u = tid; u < 1024; u += 512) {
        int rr = u >> 3;
        int c4 = (u & 7) << 4;
        *(float4*)&b1[rr * SA + c4]      = *(const float4*)(Ag + rr * WH + c4);
        *(float4*)&b1[rr * SA + c4 + 4]  = *(const float4*)(Ag + rr * WH + c4 + 4);
        *(float4*)&b1[rr * SA + c4 + 8]  = *(const float4*)(Ag + rr * WH + c4 + 8);
        *(float4*)&b1[rr * SA + c4 + 12] = *(const float4*)(Ag + rr * WH + c4 + 12);
        *(float4*)&b2[rr * SA + c4]      = *(const float4*)(Og + rr * WH + c4);
        *(float4*)&b2[rr * SA + c4 + 4]  = *(const float4*)(Og + rr * WH + c4 + 4);
        *(float4*)&b2[rr * SA + c4 + 8]  = *(const float4*)(Og + rr * WH + c4 + 8);
        *(float4*)&b2[rr * SA + c4 + 12] = *(const float4*)(Og + rr * WH + c4 + 12);
    }
    __syncthreads();

    // ---- phase 2: GEMM1  S[i][j] = sum_c A[i][c] O[j][c]; k-quad LDS.128 ----
    ull acc[4][8];
#pragma unroll
    for (int m = 0; m < 4; m++)
#pragma unroll
        for (int n = 0; n < 8; n++) acc[m][n] = 0ull;

    for (int cq = 0; cq < 32; cq++) {
        ulonglong2 av[4], bv[8];
#pragma unroll
        for (int m = 0; m < 4; m++)
            av[m] = *(const ulonglong2*)&b1[(ty + 32 * m) * SA + 4 * cq];
#pragma unroll
        for (int n = 0; n < 8; n++)
            bv[n] = *(const ulonglong2*)&b2[(tx + 16 * n) * SA + 4 * cq];
#pragma unroll
        for (int m = 0; m < 4; m++)
#pragma unroll
            for (int n = 0; n < 8; n++) {
                ffma2(acc[m][n], av[m].x, bv[n].x);
                ffma2(acc[m][n], av[m].y, bv[n].y);
            }
    }

    // ---- phase 3: register softmax along j (16 threads/row = half-warp) ----
    const float scale = 0.088388347648318447f;  // 1/sqrt(128)
    float p[4][8];
#pragma unroll
    for (int m = 0; m < 4; m++) {
        float rmax = -3.0e38f;
#pragma unroll
        for (int n = 0; n < 8; n++) {
            p[m][n] = f2sum(acc[m][n]) * scale;
            rmax = fmaxf(rmax, p[m][n]);
        }
#pragma unroll
        for (int s = 1; s < 16; s <<= 1)
            rmax = fmaxf(rmax, __shfl_xor_sync(0xFFFFFFFFu, rmax, s));
        float rsum = 0.f;
#pragma unroll
        for (int n = 0; n < 8; n++) {
            p[m][n] = __expf(p[m][n] - rmax);
            rsum += p[m][n];
        }
#pragma unroll
        for (int s = 1; s < 16; s <<= 1)
            rsum += __shfl_xor_sync(0xFFFFFFFFu, rsum, s);
        float rinv = 1.f / rsum;
#pragma unroll
        for (int n = 0; n < 8; n++) p[m][n] *= rinv;
    }
    __syncthreads();  // all GEMM1 smem reads done before overwrite

    // ---- phase 4: P natural -> b1; O^T (from gmem, L2-hot) -> b2 ----
#pragma unroll
    for (int m = 0; m < 4; m++)
#pragma unroll
        for (int n = 0; n < 8; n++)
            b1[(ty + 32 * m) * SA + tx + 16 * n] = p[m][n];
    for (int u = tid; u < 4096; u += 512) {
        int rr = u >> 5;
        int c4 = (u & 31) << 2;
        float4 vo = *(const float4*)(Og + rr * WH + c4);
        b2[(c4 + 0) * SA + rr] = vo.x;
        b2[(c4 + 1) * SA + rr] = vo.y;
        b2[(c4 + 2) * SA + rr] = vo.z;
        b2[(c4 + 3) * SA + rr] = vo.w;
    }
    __syncthreads();

    // ---- phase 5: GEMM2  M[i][c] = sum_j P[i][j] O[j][c]; k-quad LDS.128 ----
    ull acc2[4][8];
#pragma unroll
    for (int m = 0; m < 4; m++)
#pragma unroll
        for (int n = 0; n < 8; n++) acc2[m][n] = 0ull;

    for (int jq = 0; jq < 32; jq++) {
        ulonglong2 pv[4], ov[8];
#pragma unroll
        for (int m = 0; m < 4; m++)
            pv[m] = *(const ulonglong2*)&b1[(ty + 32 * m) * SA + 4 * jq];
#pragma unroll
        for (int n = 0; n < 8; n++)
            ov[n] = *(const ulonglong2*)&b2[(tx + 16 * n) * SA + 4 * jq];
#pragma unroll
        for (int m = 0; m < 4; m++)
#pragma unroll
            for (int n = 0; n < 8; n++) {
                ffma2(acc2[m][n], pv[m].x, ov[n].x);
                ffma2(acc2[m][n], pv[m].y, ov[n].y);
            }
    }

    // ---- phase 6: fused distance (A from gmem, L2-hot) + block reduce ----
    float dsum = 0.f;
#pragma unroll
    for (int m = 0; m < 4; m++)
#pragma unroll
        for (int n = 0; n < 8; n++) {
            float a = Ag[(ty + 32 * m) * WH + tx + 16 * n];
            float d = a - f2sum(acc2[m][n]);
            dsum += d * d;
        }
    xch[tid] = dsum;
    __syncthreads();
    for (int st = 256; st > 0; st >>= 1) {
        if (tid < st) xch[tid] += xch[tid + st];
        __syncthreads();
    }
    if (tid == 0) g_dd[blk] = xch[0];
}

// ===========================================================================
// Kernel 5: final margin ranking loss
// ===========================================================================
__global__ void loss_kernel(float* __restrict__ out) {
    int tid = threadIdx.x;
    float s = 0.f;
    for (int b = tid; b < N_SAMP; b += 256) {
        float dap = sqrtf(g_dd[2 * b]);
        float dan = sqrtf(g_dd[2 * b + 1]);
        float v = dap - dan + 0.3f;
        s += (v > 0.f) ? v : 0.f;
    }
    __shared__ float red[256];
    red[tid] = s;
    __syncthreads();
    for (int st = 128; st > 0; st >>= 1) {
        if (tid < st) red[tid] += red[tid + st];
        __syncthreads();
    }
    if (tid == 0) out[0] = red[0] * (1.0f / (float)N_SAMP);
}

// ===========================================================================
extern "C" void kernel_launch(void* const* d_in, const int* in_sizes, int n_in,
                              void* d_out, int out_size) {
    const float* X;
    const int*   T;
    if (n_in >= 2 && in_sizes[0] == N_SAMP && in_sizes[1] != N_SAMP) {
        T = (const int*)d_in[0];
        X = (const float*)d_in[1];
    } else {
        X = (const float*)d_in[0];
        T = (const int*)d_in[1];
    }

    const int smem_attn = 2 * 128 * SA * (int)sizeof(float);  // 135168 B
    cudaFuncSetAttribute(attn_kernel, cudaFuncAttributeMaxDynamicSharedMemorySize,
                         smem_attn);

    gram_f2<<<144, 256>>>(X);
    gram_reduce<<<36, 256>>>();
    mine_kernel<<<N_SAMP, 256>>>(T);
    attn_kernel<<<2 * N_SAMP, 512, smem_attn>>>(X);
    loss_kernel<<<1, 256>>>((float*)d_out);
}

// round 12
// speedup vs baseline: 1.0430x; 1.0430x over previous
#include <cuda_runtime.h>
#include <math.h>
#include <stdint.h>

#define N_SAMP 1024
#define D      16384
#define WH     128
#define SA     130   // attn smem stride (words); 2*tx mod 32 distinct -> conflict-free LDS.64
#define GSA    18    // gram stage row stride (words)

typedef unsigned long long ull;

// ---- device scratch (no allocations allowed) ----
__device__ float g_gram[N_SAMP * N_SAMP];
__device__ float g_part[144 * 16384];      // split-K partial tiles
__device__ float g_sq[N_SAMP];
__device__ int   g_hp[N_SAMP];
__device__ int   g_hn[N_SAMP];
__device__ float g_dd[2 * N_SAMP];

// ---- packed fp32x2 FMA (Blackwell dual fp32; exact fp32 math) ----
__device__ __forceinline__ void ffma2(ull& d, ull a, ull b) {
    asm("fma.rn.f32x2 %0, %1, %2, %0;" : "+l"(d) : "l"(a), "l"(b));
}
__device__ __forceinline__ float f2sum(ull v) {
    return __uint_as_float((unsigned)(v & 0xFFFFFFFFu)) +
           __uint_as_float((unsigned)(v >> 32));
}

// ===========================================================================
// Kernel 2: Gram GEMM with FFMA2 (unchanged: measured ~97% of FFMA2 floor).
// 36 triangular 128x128 tiles x 4 K-splits = 144 blocks (one wave).
// ===========================================================================
__global__ __launch_bounds__(256, 1)
void gram_f2(const float* __restrict__ X) {
    __shared__ __align__(16) float As[2][128 * GSA];
    __shared__ __align__(16) float Bs[2][128 * GSA];

    const int tid = threadIdx.x;
    const int tx  = tid & 15;
    const int ty  = tid >> 4;

    int blk = blockIdx.x;
    int split = blk / 36;
    int tile  = blk % 36;
    int r = tile, bi = 0;
    while (r >= 8 - bi) { r -= 8 - bi; bi++; }
    int bj = bi + r;

    const float* Ag = X + (size_t)(bi * 128) * D + split * 4096;
    const float* Bg = X + (size_t)(bj * 128) * D + split * 4096;

    const int lr0 = tid >> 2;
    const int lr1 = lr0 + 64;
    const int lc  = (tid & 3) << 2;

    ull acc[8][8];
#pragma unroll
    for (int m = 0; m < 8; m++)
#pragma unroll
        for (int n = 0; n < 8; n++) acc[m][n] = 0ull;

    float4 pa0 = *(const float4*)(Ag + (size_t)lr0 * D + lc);
    float4 pa1 = *(const float4*)(Ag + (size_t)lr1 * D + lc);
    float4 pb0 = *(const float4*)(Bg + (size_t)lr0 * D + lc);
    float4 pb1 = *(const float4*)(Bg + (size_t)lr1 * D + lc);
    *(float2*)&As[0][lr0 * GSA + lc]     = make_float2(pa0.x, pa0.y);
    *(float2*)&As[0][lr0 * GSA + lc + 2] = make_float2(pa0.z, pa0.w);
    *(float2*)&As[0][lr1 * GSA + lc]     = make_float2(pa1.x, pa1.y);
    *(float2*)&As[0][lr1 * GSA + lc + 2] = make_float2(pa1.z, pa1.w);
    *(float2*)&Bs[0][lr0 * GSA + lc]     = make_float2(pb0.x, pb0.y);
    *(float2*)&Bs[0][lr0 * GSA + lc + 2] = make_float2(pb0.z, pb0.w);
    *(float2*)&Bs[0][lr1 * GSA + lc]     = make_float2(pb1.x, pb1.y);
    *(float2*)&Bs[0][lr1 * GSA + lc + 2] = make_float2(pb1.z, pb1.w);
    __syncthreads();

    const int NC = 4096 / 16;
    int cur = 0;
    for (int c = 0; c < NC; c++) {
        bool more = (c + 1) < NC;
        if (more) {
            int kk = (c + 1) * 16;
            pa0 = *(const float4*)(Ag + (size_t)lr0 * D + kk + lc);
            pa1 = *(const float4*)(Ag + (size_t)lr1 * D + kk + lc);
            pb0 = *(const float4*)(Bg + (size_t)lr0 * D + kk + lc);
            pb1 = *(const float4*)(Bg + (size_t)lr1 * D + kk + lc);
        }
#pragma unroll
        for (int kp = 0; kp < 8; kp++) {
            ull av[8], bv[8];
#pragma unroll
            for (int m = 0; m < 8; m++)
                av[m] = *(const ull*)&As[cur][(ty + 16 * m) * GSA + 2 * kp];
#pragma unroll
            for (int n = 0; n < 8; n++)
                bv[n] = *(const ull*)&Bs[cur][(tx + 16 * n) * GSA + 2 * kp];
#pragma unroll
            for (int m = 0; m < 8; m++)
#pragma unroll
                for (int n = 0; n < 8; n++) ffma2(acc[m][n], av[m], bv[n]);
        }
        if (more) {
            int nxt = cur ^ 1;
            *(float2*)&As[nxt][lr0 * GSA + lc]     = make_float2(pa0.x, pa0.y);
            *(float2*)&As[nxt][lr0 * GSA + lc + 2] = make_float2(pa0.z, pa0.w);
            *(float2*)&As[nxt][lr1 * GSA + lc]     = make_float2(pa1.x, pa1.y);
            *(float2*)&As[nxt][lr1 * GSA + lc + 2] = make_float2(pa1.z, pa1.w);
            *(float2*)&Bs[nxt][lr0 * GSA + lc]     = make_float2(pb0.x, pb0.y);
            *(float2*)&Bs[nxt][lr0 * GSA + lc + 2] = make_float2(pb0.z, pb0.w);
            *(float2*)&Bs[nxt][lr1 * GSA + lc]     = make_float2(pb1.x, pb1.y);
            *(float2*)&Bs[nxt][lr1 * GSA + lc + 2] = make_float2(pb1.z, pb1.w);
            __syncthreads();
            cur = nxt;
        }
    }

    float* dst = g_part + (size_t)blk * 16384;
#pragma unroll
    for (int m = 0; m < 8; m++)
#pragma unroll
        for (int n = 0; n < 8; n++)
            dst[(ty + 16 * m) * 128 + (tx + 16 * n)] = f2sum(acc[m][n]);
}

// ===========================================================================
// Kernel 2b: reduce split-K partials, write G, mirror, and diagonal -> g_sq
// ===========================================================================
__global__ void gram_reduce() {
    int tile = blockIdx.x;
    int r = tile, bi = 0;
    while (r >= 8 - bi) { r -= 8 - bi; bi++; }
    int bj = bi + r;
    const float* p0 = g_part + (size_t)(0 * 36 + tile) * 16384;
    const float* p1 = g_part + (size_t)(1 * 36 + tile) * 16384;
    const float* p2 = g_part + (size_t)(2 * 36 + tile) * 16384;
    const float* p3 = g_part + (size_t)(3 * 36 + tile) * 16384;
    for (int u = threadIdx.x; u < 16384; u += 256) {
        float s = p0[u] + p1[u] + p2[u] + p3[u];
        int rr = u >> 7, cc = u & 127;
        int i = bi * 128 + rr, j = bj * 128 + cc;
        g_gram[i * N_SAMP + j] = s;
        if (bi != bj) g_gram[j * N_SAMP + i] = s;
        else if (rr == cc) g_sq[i] = s;   // diagonal = squared norm
    }
}

// ===========================================================================
// Kernel 3: hard mining
// ===========================================================================
__global__ void mine_kernel(const int* __restrict__ targets) {
    int i   = blockIdx.x;
    int tid = threadIdx.x;
    int tg  = targets[i];

    float bpv = -3.0e38f; int bpi = 0;
    float bnv =  3.0e38f; int bni = 0;
    for (int j = tid; j < N_SAMP; j += 256) {
        float val = g_sq[j] - 2.f * g_gram[i * N_SAMP + j];
        if (targets[j] == tg) {
            if (val > bpv || (val == bpv && j < bpi)) { bpv = val; bpi = j; }
        } else {
            if (val < bnv || (val == bnv && j < bni)) { bnv = val; bni = j; }
        }
    }
    __shared__ float spv[256]; __shared__ int spi[256];
    __shared__ float snv[256]; __shared__ int sni[256];
    spv[tid] = bpv; spi[tid] = bpi; snv[tid] = bnv; sni[tid] = bni;
    __syncthreads();
    for (int st = 128; st > 0; st >>= 1) {
        if (tid < st) {
            float ov = spv[tid + st]; int oi = spi[tid + st];
            if (ov > spv[tid] || (ov == spv[tid] && oi < spi[tid])) { spv[tid] = ov; spi[tid] = oi; }
            float nv = snv[tid + st]; int ni2 = sni[tid + st];
            if (nv < snv[tid] || (nv == snv[tid] && ni2 < sni[tid])) { snv[tid] = nv; sni[tid] = ni2; }
        }
        __syncthreads();
    }
    if (tid == 0) { g_hp[i] = spi[0]; g_hn[i] = sni[0]; }
}

// ===========================================================================
// Kernel 4: attention + distance. 256 threads, 8x8 microtile (gram-proven
// shape: LDS:FFMA2 ratio 16/64), k-pair LDS.64 @ SA=130 (conflict-free),
// register-double-buffered GEMM pipeline, register softmax (half-warp
// shuffles), fused distance epilogue.
// b1 = A natural -> P natural; b2 = O natural -> O^T.
// ===========================================================================
__global__ __launch_bounds__(256, 1)
void attn_kernel(const float* __restrict__ X) {
    extern __shared__ __align__(16) float sm[];
    float* b1 = sm;              // A natural -> P natural
    float* b2 = sm + 128 * SA;   // O natural -> O^T
    __shared__ float xch[256];

    const int tid = threadIdx.x;
    const int tx  = tid & 15;       // j/c index: tx + 16n, n<8
    const int ty  = tid >> 4;       // i index:   ty + 16m, m<8
    const int blk = blockIdx.x;
    const int bb  = blk >> 1;
    const int oidx = (blk & 1) ? g_hn[bb] : g_hp[bb];
    const float* Ag = X + (size_t)bb * D;
    const float* Og = X + (size_t)oidx * D;

    // ---- phase 1: A natural -> b1, O natural -> b2 ----
    for (int u = tid; u < 1024; u += 256) {
        int rr = u >> 3;
        int c4 = (u & 7) << 4;
        float4 va0 = *(const float4*)(Ag + rr * WH + c4);
        float4 va1 = *(const float4*)(Ag + rr * WH + c4 + 4);
        float4 va2 = *(const float4*)(Ag + rr * WH + c4 + 8);
        float4 va3 = *(const float4*)(Ag + rr * WH + c4 + 12);
        float4 vo0 = *(const float4*)(Og + rr * WH + c4);
        float4 vo1 = *(const float4*)(Og + rr * WH + c4 + 4);
        float4 vo2 = *(const float4*)(Og + rr * WH + c4 + 8);
        float4 vo3 = *(const float4*)(Og + rr * WH + c4 + 12);
        float* d1 = &b1[rr * SA + c4];
        float* d2 = &b2[rr * SA + c4];
        *(float2*)(d1 + 0)  = make_float2(va0.x, va0.y);
        *(float2*)(d1 + 2)  = make_float2(va0.z, va0.w);
        *(float2*)(d1 + 4)  = make_float2(va1.x, va1.y);
        *(float2*)(d1 + 6)  = make_float2(va1.z, va1.w);
        *(float2*)(d1 + 8)  = make_float2(va2.x, va2.y);
        *(float2*)(d1 + 10) = make_float2(va2.z, va2.w);
        *(float2*)(d1 + 12) = make_float2(va3.x, va3.y);
        *(float2*)(d1 + 14) = make_float2(va3.z, va3.w);
        *(float2*)(d2 + 0)  = make_float2(vo0.x, vo0.y);
        *(float2*)(d2 + 2)  = make_float2(vo0.z, vo0.w);
        *(float2*)(d2 + 4)  = make_float2(vo1.x, vo1.y);
        *(float2*)(d2 + 6)  = make_float2(vo1.z, vo1.w);
        *(float2*)(d2 + 8)  = make_float2(vo2.x, vo2.y);
        *(float2*)(d2 + 10) = make_float2(vo2.z, vo2.w);
        *(float2*)(d2 + 12) = make_float2(vo3.x, vo3.y);
        *(float2*)(d2 + 14) = make_float2(vo3.z, vo3.w);
    }
    __syncthreads();

    ull acc[8][8];
    ull av0[8], bv0[8], av1[8], bv1[8];

    // ---- phase 2: GEMM1  S[i][j] = sum_c A[i][c] O[j][c]; reg-pipelined ----
#pragma unroll
    for (int m = 0; m < 8; m++)
#pragma unroll
        for (int n = 0; n < 8; n++) acc[m][n] = 0ull;

#pragma unroll
    for (int m = 0; m < 8; m++) av0[m] = *(const ull*)&b1[(ty + 16 * m) * SA];
#pragma unroll
    for (int n = 0; n < 8; n++) bv0[n] = *(const ull*)&b2[(tx + 16 * n) * SA];

#pragma unroll 1
    for (int cp = 0; cp < 64; cp += 2) {
#pragma unroll
        for (int m = 0; m < 8; m++)
            av1[m] = *(const ull*)&b1[(ty + 16 * m) * SA + 2 * cp + 2];
#pragma unroll
        for (int n = 0; n < 8; n++)
            bv1[n] = *(const ull*)&b2[(tx + 16 * n) * SA + 2 * cp + 2];
#pragma unroll
        for (int m = 0; m < 8; m++)
#pragma unroll
            for (int n = 0; n < 8; n++) ffma2(acc[m][n], av0[m], bv0[n]);
        if (cp < 62) {
#pragma unroll
            for (int m = 0; m < 8; m++)
                av0[m] = *(const ull*)&b1[(ty + 16 * m) * SA + 2 * cp + 4];
#pragma unroll
            for (int n = 0; n < 8; n++)
                bv0[n] = *(const ull*)&b2[(tx + 16 * n) * SA + 2 * cp + 4];
        }
#pragma unroll
        for (int m = 0; m < 8; m++)
#pragma unroll
            for (int n = 0; n < 8; n++) ffma2(acc[m][n], av1[m], bv1[n]);
    }

    // ---- phase 3: register softmax along j (16 threads/row = half-warp) ----
    const float scale = 0.088388347648318447f;  // 1/sqrt(128)
    float p[8][8];
#pragma unroll
    for (int m = 0; m < 8; m++) {
        float rmax = -3.0e38f;
#pragma unroll
        for (int n = 0; n < 8; n++) {
            p[m][n] = f2sum(acc[m][n]) * scale;
            rmax = fmaxf(rmax, p[m][n]);
        }
#pragma unroll
        for (int s = 1; s < 16; s <<= 1)
            rmax = fmaxf(rmax, __shfl_xor_sync(0xFFFFFFFFu, rmax, s));
        float rsum = 0.f;
#pragma unroll
        for (int n = 0; n < 8; n++) {
            p[m][n] = __expf(p[m][n] - rmax);
            rsum += p[m][n];
        }
#pragma unroll
        for (int s = 1; s < 16; s <<= 1)
            rsum += __shfl_xor_sync(0xFFFFFFFFu, rsum, s);
        float rinv = 1.f / rsum;
#pragma unroll
        for (int n = 0; n < 8; n++) p[m][n] *= rinv;
    }
    __syncthreads();  // all GEMM1 smem reads done before overwrite

    // ---- phase 4: P natural -> b1; O^T (from gmem, L2-hot) -> b2 ----
#pragma unroll
    for (int m = 0; m < 8; m++)
#pragma unroll
        for (int n = 0; n < 8; n++)
            b1[(ty + 16 * m) * SA + tx + 16 * n] = p[m][n];
    for (int u = tid; u < 4096; u += 256) {
        int rr = u >> 5;
        int c4 = (u & 31) << 2;
        float4 vo = *(const float4*)(Og + rr * WH + c4);
        b2[(c4 + 0) * SA + rr] = vo.x;
        b2[(c4 + 1) * SA + rr] = vo.y;
        b2[(c4 + 2) * SA + rr] = vo.z;
        b2[(c4 + 3) * SA + rr] = vo.w;
    }
    __syncthreads();

    // ---- phase 5: GEMM2  M[i][c] = sum_j P[i][j] O[j][c]; reg-pipelined ----
#pragma unroll
    for (int m = 0; m < 8; m++)
#pragma unroll
        for (int n = 0; n < 8; n++) acc[m][n] = 0ull;

#pragma unroll
    for (int m = 0; m < 8; m++) av0[m] = *(const ull*)&b1[(ty + 16 * m) * SA];
#pragma unroll
    for (int n = 0; n < 8; n++) bv0[n] = *(const ull*)&b2[(tx + 16 * n) * SA];

#pragma unroll 1
    for (int jp = 0; jp < 64; jp += 2) {
#pragma unroll
        for (int m = 0; m < 8; m++)
            av1[m] = *(const ull*)&b1[(ty + 16 * m) * SA + 2 * jp + 2];
#pragma unroll
        for (int n = 0; n < 8; n++)
            bv1[n] = *(const ull*)&b2[(tx + 16 * n) * SA + 2 * jp + 2];
#pragma unroll
        for (int m = 0; m < 8; m++)
#pragma unroll
            for (int n = 0; n < 8; n++) ffma2(acc[m][n], av0[m], bv0[n]);
        if (jp < 62) {
#pragma unroll
            for (int m = 0; m < 8; m++)
                av0[m] = *(const ull*)&b1[(ty + 16 * m) * SA + 2 * jp + 4];
#pragma unroll
            for (int n = 0; n < 8; n++)
                bv0[n] = *(const ull*)&b2[(tx + 16 * n) * SA + 2 * jp + 4];
        }
#pragma unroll
        for (int m = 0; m < 8; m++)
#pragma unroll
            for (int n = 0; n < 8; n++) ffma2(acc[m][n], av1[m], bv1[n]);
    }

    // ---- phase 6: fused distance (A from gmem, L2-hot) + block reduce ----
    float dsum = 0.f;
#pragma unroll
    for (int m = 0; m < 8; m++)
#pragma unroll
        for (int n = 0; n < 8; n++) {
            float a = Ag[(ty + 16 * m) * WH + tx + 16 * n];
            float d = a - f2sum(acc[m][n]);
            dsum += d * d;
        }
    xch[tid] = dsum;
    __syncthreads();
    for (int st = 128; st > 0; st >>= 1) {
        if (tid < st) xch[tid] += xch[tid + st];
        __syncthreads();
    }
    if (tid == 0) g_dd[blk] = xch[0];
}

// ===========================================================================
// Kernel 5: final margin ranking loss
// ===========================================================================
__global__ void loss_kernel(float* __restrict__ out) {
    int tid = threadIdx.x;
    float s = 0.f;
    for (int b = tid; b < N_SAMP; b += 256) {
        float dap = sqrtf(g_dd[2 * b]);
        float dan = sqrtf(g_dd[2 * b + 1]);
        float v = dap - dan + 0.3f;
        s += (v > 0.f) ? v : 0.f;
    }
    __shared__ float red[256];
    red[tid] = s;
    __syncthreads();
    for (int st = 128; st > 0; st >>= 1) {
        if (tid < st) red[tid] += red[tid + st];
        __syncthreads();
    }
    if (tid == 0) out[0] = red[0] * (1.0f / (float)N_SAMP);
}

// ===========================================================================
extern "C" void kernel_launch(void* const* d_in, const int* in_sizes, int n_in,
                              void* d_out, int out_size) {
    const float* X;
    const int*   T;
    if (n_in >= 2 && in_sizes[0] == N_SAMP && in_sizes[1] != N_SAMP) {
        T = (const int*)d_in[0];
        X = (const float*)d_in[1];
    } else {
        X = (const float*)d_in[0];
        T = (const int*)d_in[1];
    }

    const int smem_attn = 2 * 128 * SA * (int)sizeof(float);  // 133120 B
    cudaFuncSetAttribute(attn_kernel, cudaFuncAttributeMaxDynamicSharedMemorySize,
                         smem_attn);

    gram_f2<<<144, 256>>>(X);
    gram_reduce<<<36, 256>>>();
    mine_kernel<<<N_SAMP, 256>>>(T);
    attn_kernel<<<2 * N_SAMP, 256, smem_attn>>>(X);
    loss_kernel<<<1, 256>>>((float*)d_out);
}

// round 13
// speedup vs baseline: 1.0727x; 1.0285x over previous
#include <cuda_runtime.h>
#include <math.h>
#include <stdint.h>

#define N_SAMP 1024
#define D      16384
#define WH     128
#define SA     130   // attn smem stride (words); 2*tx mod 32 distinct -> conflict-free LDS.64
#define GSA    18    // gram stage row stride (words)

typedef unsigned long long ull;

// ---- device scratch (no allocations allowed) ----
__device__ float g_gram[N_SAMP * N_SAMP];
__device__ float g_part[144 * 16384];      // split-K partial tiles
__device__ float g_sq[N_SAMP];
__device__ int   g_hp[N_SAMP];
__device__ int   g_hn[N_SAMP];
__device__ float g_dd[2 * N_SAMP];

// ---- packed fp32x2 FMA (Blackwell dual fp32; exact fp32 math) ----
__device__ __forceinline__ void ffma2(ull& d, ull a, ull b) {
    asm("fma.rn.f32x2 %0, %1, %2, %0;" : "+l"(d) : "l"(a), "l"(b));
}
__device__ __forceinline__ float f2sum(ull v) {
    return __uint_as_float((unsigned)(v & 0xFFFFFFFFu)) +
           __uint_as_float((unsigned)(v >> 32));
}

// ===========================================================================
// Kernel 2: Gram GEMM with FFMA2 (unchanged: measured ~97% of FFMA2 floor).
// 36 triangular 128x128 tiles x 4 K-splits = 144 blocks (one wave).
// ===========================================================================
__global__ __launch_bounds__(256, 1)
void gram_f2(const float* __restrict__ X) {
    __shared__ __align__(16) float As[2][128 * GSA];
    __shared__ __align__(16) float Bs[2][128 * GSA];

    const int tid = threadIdx.x;
    const int tx  = tid & 15;
    const int ty  = tid >> 4;

    int blk = blockIdx.x;
    int split = blk / 36;
    int tile  = blk % 36;
    int r = tile, bi = 0;
    while (r >= 8 - bi) { r -= 8 - bi; bi++; }
    int bj = bi + r;

    const float* Ag = X + (size_t)(bi * 128) * D + split * 4096;
    const float* Bg = X + (size_t)(bj * 128) * D + split * 4096;

    const int lr0 = tid >> 2;
    const int lr1 = lr0 + 64;
    const int lc  = (tid & 3) << 2;

    ull acc[8][8];
#pragma unroll
    for (int m = 0; m < 8; m++)
#pragma unroll
        for (int n = 0; n < 8; n++) acc[m][n] = 0ull;

    float4 pa0 = *(const float4*)(Ag + (size_t)lr0 * D + lc);
    float4 pa1 = *(const float4*)(Ag + (size_t)lr1 * D + lc);
    float4 pb0 = *(const float4*)(Bg + (size_t)lr0 * D + lc);
    float4 pb1 = *(const float4*)(Bg + (size_t)lr1 * D + lc);
    *(float2*)&As[0][lr0 * GSA + lc]     = make_float2(pa0.x, pa0.y);
    *(float2*)&As[0][lr0 * GSA + lc + 2] = make_float2(pa0.z, pa0.w);
    *(float2*)&As[0][lr1 * GSA + lc]     = make_float2(pa1.x, pa1.y);
    *(float2*)&As[0][lr1 * GSA + lc + 2] = make_float2(pa1.z, pa1.w);
    *(float2*)&Bs[0][lr0 * GSA + lc]     = make_float2(pb0.x, pb0.y);
    *(float2*)&Bs[0][lr0 * GSA + lc + 2] = make_float2(pb0.z, pb0.w);
    *(float2*)&Bs[0][lr1 * GSA + lc]     = make_float2(pb1.x, pb1.y);
    *(float2*)&Bs[0][lr1 * GSA + lc + 2] = make_float2(pb1.z, pb1.w);
    __syncthreads();

    const int NC = 4096 / 16;
    int cur = 0;
    for (int c = 0; c < NC; c++) {
        bool more = (c + 1) < NC;
        if (more) {
            int kk = (c + 1) * 16;
            pa0 = *(const float4*)(Ag + (size_t)lr0 * D + kk + lc);
            pa1 = *(const float4*)(Ag + (size_t)lr1 * D + kk + lc);
            pb0 = *(const float4*)(Bg + (size_t)lr0 * D + kk + lc);
            pb1 = *(const float4*)(Bg + (size_t)lr1 * D + kk + lc);
        }
#pragma unroll
        for (int kp = 0; kp < 8; kp++) {
            ull av[8], bv[8];
#pragma unroll
            for (int m = 0; m < 8; m++)
                av[m] = *(const ull*)&As[cur][(ty + 16 * m) * GSA + 2 * kp];
#pragma unroll
            for (int n = 0; n < 8; n++)
                bv[n] = *(const ull*)&Bs[cur][(tx + 16 * n) * GSA + 2 * kp];
#pragma unroll
            for (int m = 0; m < 8; m++)
#pragma unroll
                for (int n = 0; n < 8; n++) ffma2(acc[m][n], av[m], bv[n]);
        }
        if (more) {
            int nxt = cur ^ 1;
            *(float2*)&As[nxt][lr0 * GSA + lc]     = make_float2(pa0.x, pa0.y);
            *(float2*)&As[nxt][lr0 * GSA + lc + 2] = make_float2(pa0.z, pa0.w);
            *(float2*)&As[nxt][lr1 * GSA + lc]     = make_float2(pa1.x, pa1.y);
            *(float2*)&As[nxt][lr1 * GSA + lc + 2] = make_float2(pa1.z, pa1.w);
            *(float2*)&Bs[nxt][lr0 * GSA + lc]     = make_float2(pb0.x, pb0.y);
            *(float2*)&Bs[nxt][lr0 * GSA + lc + 2] = make_float2(pb0.z, pb0.w);
            *(float2*)&Bs[nxt][lr1 * GSA + lc]     = make_float2(pb1.x, pb1.y);
            *(float2*)&Bs[nxt][lr1 * GSA + lc + 2] = make_float2(pb1.z, pb1.w);
            __syncthreads();
            cur = nxt;
        }
    }

    float* dst = g_part + (size_t)blk * 16384;
#pragma unroll
    for (int m = 0; m < 8; m++)
#pragma unroll
        for (int n = 0; n < 8; n++)
            dst[(ty + 16 * m) * 128 + (tx + 16 * n)] = f2sum(acc[m][n]);
}

// ===========================================================================
// Kernel 2b: reduce split-K partials, write G, mirror, and diagonal -> g_sq
// ===========================================================================
__global__ void gram_reduce() {
    int tile = blockIdx.x;
    int r = tile, bi = 0;
    while (r >= 8 - bi) { r -= 8 - bi; bi++; }
    int bj = bi + r;
    const float* p0 = g_part + (size_t)(0 * 36 + tile) * 16384;
    const float* p1 = g_part + (size_t)(1 * 36 + tile) * 16384;
    const float* p2 = g_part + (size_t)(2 * 36 + tile) * 16384;
    const float* p3 = g_part + (size_t)(3 * 36 + tile) * 16384;
    for (int u = threadIdx.x; u < 16384; u += 256) {
        float s = p0[u] + p1[u] + p2[u] + p3[u];
        int rr = u >> 7, cc = u & 127;
        int i = bi * 128 + rr, j = bj * 128 + cc;
        g_gram[i * N_SAMP + j] = s;
        if (bi != bj) g_gram[j * N_SAMP + i] = s;
        else if (rr == cc) g_sq[i] = s;   // diagonal = squared norm
    }
}

// ===========================================================================
// Kernel 3: hard mining
// ===========================================================================
__global__ void mine_kernel(const int* __restrict__ targets) {
    int i   = blockIdx.x;
    int tid = threadIdx.x;
    int tg  = targets[i];

    float bpv = -3.0e38f; int bpi = 0;
    float bnv =  3.0e38f; int bni = 0;
    for (int j = tid; j < N_SAMP; j += 256) {
        float val = g_sq[j] - 2.f * g_gram[i * N_SAMP + j];
        if (targets[j] == tg) {
            if (val > bpv || (val == bpv && j < bpi)) { bpv = val; bpi = j; }
        } else {
            if (val < bnv || (val == bnv && j < bni)) { bnv = val; bni = j; }
        }
    }
    __shared__ float spv[256]; __shared__ int spi[256];
    __shared__ float snv[256]; __shared__ int sni[256];
    spv[tid] = bpv; spi[tid] = bpi; snv[tid] = bnv; sni[tid] = bni;
    __syncthreads();
    for (int st = 128; st > 0; st >>= 1) {
        if (tid < st) {
            float ov = spv[tid + st]; int oi = spi[tid + st];
            if (ov > spv[tid] || (ov == spv[tid] && oi < spi[tid])) { spv[tid] = ov; spi[tid] = oi; }
            float nv = snv[tid + st]; int ni2 = sni[tid + st];
            if (nv < snv[tid] || (nv == snv[tid] && ni2 < sni[tid])) { snv[tid] = nv; sni[tid] = ni2; }
        }
        __syncthreads();
    }
    if (tid == 0) { g_hp[i] = spi[0]; g_hn[i] = sni[0]; }
}

// ===========================================================================
// Kernel 4: attention + distance. 256 threads, 8x8 microtile, k-pair LDS.64,
// gram-style GEMM loops: outer 8 chunks, inner 8 k-pairs FULLY UNROLLED
// (straight-line 128 LDS + 512 ffma2) so ptxas can hoist loads freely.
// Register softmax (half-warp shuffles), fused distance epilogue.
// b1 = A natural -> P natural; b2 = O natural -> O^T.
// ===========================================================================
__global__ __launch_bounds__(256, 1)
void attn_kernel(const float* __restrict__ X) {
    extern __shared__ __align__(16) float sm[];
    float* b1 = sm;              // A natural -> P natural
    float* b2 = sm + 128 * SA;   // O natural -> O^T
    __shared__ float xch[256];

    const int tid = threadIdx.x;
    const int tx  = tid & 15;       // j/c index: tx + 16n, n<8
    const int ty  = tid >> 4;       // i index:   ty + 16m, m<8
    const int blk = blockIdx.x;
    const int bb  = blk >> 1;
    const int oidx = (blk & 1) ? g_hn[bb] : g_hp[bb];
    const float* Ag = X + (size_t)bb * D;
    const float* Og = X + (size_t)oidx * D;

    // ---- phase 1: A natural -> b1, O natural -> b2 ----
    for (int u = tid; u < 1024; u += 256) {
        int rr = u >> 3;
        int c4 = (u & 7) << 4;
        float4 va0 = *(const float4*)(Ag + rr * WH + c4);
        float4 va1 = *(const float4*)(Ag + rr * WH + c4 + 4);
        float4 va2 = *(const float4*)(Ag + rr * WH + c4 + 8);
        float4 va3 = *(const float4*)(Ag + rr * WH + c4 + 12);
        float4 vo0 = *(const float4*)(Og + rr * WH + c4);
        float4 vo1 = *(const float4*)(Og + rr * WH + c4 + 4);
        float4 vo2 = *(const float4*)(Og + rr * WH + c4 + 8);
        float4 vo3 = *(const float4*)(Og + rr * WH + c4 + 12);
        float* d1 = &b1[rr * SA + c4];
        float* d2 = &b2[rr * SA + c4];
        *(float2*)(d1 + 0)  = make_float2(va0.x, va0.y);
        *(float2*)(d1 + 2)  = make_float2(va0.z, va0.w);
        *(float2*)(d1 + 4)  = make_float2(va1.x, va1.y);
        *(float2*)(d1 + 6)  = make_float2(va1.z, va1.w);
        *(float2*)(d1 + 8)  = make_float2(va2.x, va2.y);
        *(float2*)(d1 + 10) = make_float2(va2.z, va2.w);
        *(float2*)(d1 + 12) = make_float2(va3.x, va3.y);
        *(float2*)(d1 + 14) = make_float2(va3.z, va3.w);
        *(float2*)(d2 + 0)  = make_float2(vo0.x, vo0.y);
        *(float2*)(d2 + 2)  = make_float2(vo0.z, vo0.w);
        *(float2*)(d2 + 4)  = make_float2(vo1.x, vo1.y);
        *(float2*)(d2 + 6)  = make_float2(vo1.z, vo1.w);
        *(float2*)(d2 + 8)  = make_float2(vo2.x, vo2.y);
        *(float2*)(d2 + 10) = make_float2(vo2.z, vo2.w);
        *(float2*)(d2 + 12) = make_float2(vo3.x, vo3.y);
        *(float2*)(d2 + 14) = make_float2(vo3.z, vo3.w);
    }
    __syncthreads();

    ull acc[8][8];

    // ---- phase 2: GEMM1  S[i][j] = sum_c A[i][c] O[j][c]; gram-style ----
#pragma unroll
    for (int m = 0; m < 8; m++)
#pragma unroll
        for (int n = 0; n < 8; n++) acc[m][n] = 0ull;

#pragma unroll 1
    for (int ch = 0; ch < 8; ch++) {
        const float* p1r = &b1[ty * SA + 16 * ch];
        const float* p2r = &b2[tx * SA + 16 * ch];
#pragma unroll
        for (int kp = 0; kp < 8; kp++) {
            ull av[8], bv[8];
#pragma unroll
            for (int m = 0; m < 8; m++)
                av[m] = *(const ull*)(p1r + (16 * m) * SA + 2 * kp);
#pragma unroll
            for (int n = 0; n < 8; n++)
                bv[n] = *(const ull*)(p2r + (16 * n) * SA + 2 * kp);
#pragma unroll
            for (int m = 0; m < 8; m++)
#pragma unroll
                for (int n = 0; n < 8; n++) ffma2(acc[m][n], av[m], bv[n]);
        }
    }

    // ---- phase 3: register softmax along j (16 threads/row = half-warp) ----
    const float scale = 0.088388347648318447f;  // 1/sqrt(128)
    float p[8][8];
#pragma unroll
    for (int m = 0; m < 8; m++) {
        float rmax = -3.0e38f;
#pragma unroll
        for (int n = 0; n < 8; n++) {
            p[m][n] = f2sum(acc[m][n]) * scale;
            rmax = fmaxf(rmax, p[m][n]);
        }
#pragma unroll
        for (int s = 1; s < 16; s <<= 1)
            rmax = fmaxf(rmax, __shfl_xor_sync(0xFFFFFFFFu, rmax, s));
        float rsum = 0.f;
#pragma unroll
        for (int n = 0; n < 8; n++) {
            p[m][n] = __expf(p[m][n] - rmax);
            rsum += p[m][n];
        }
#pragma unroll
        for (int s = 1; s < 16; s <<= 1)
            rsum += __shfl_xor_sync(0xFFFFFFFFu, rsum, s);
        float rinv = 1.f / rsum;
#pragma unroll
        for (int n = 0; n < 8; n++) p[m][n] *= rinv;
    }
    __syncthreads();  // all GEMM1 smem reads done before overwrite

    // ---- phase 4: P natural -> b1; O^T (from gmem, L2-hot) -> b2 ----
#pragma unroll
    for (int m = 0; m < 8; m++)
#pragma unroll
        for (int n = 0; n < 8; n++)
            b1[(ty + 16 * m) * SA + tx + 16 * n] = p[m][n];
    for (int u = tid; u < 4096; u += 256) {
        int rr = u >> 5;
        int c4 = (u & 31) << 2;
        float4 vo = *(const float4*)(Og + rr * WH + c4);
        b2[(c4 + 0) * SA + rr] = vo.x;
        b2[(c4 + 1) * SA + rr] = vo.y;
        b2[(c4 + 2) * SA + rr] = vo.z;
        b2[(c4 + 3) * SA + rr] = vo.w;
    }
    __syncthreads();

    // ---- phase 5: GEMM2  M[i][c] = sum_j P[i][j] O[j][c]; gram-style ----
#pragma unroll
    for (int m = 0; m < 8; m++)
#pragma unroll
        for (int n = 0; n < 8; n++) acc[m][n] = 0ull;

#pragma unroll 1
    for (int ch = 0; ch < 8; ch++) {
        const float* p1r = &b1[ty * SA + 16 * ch];
        const float* p2r = &b2[tx * SA + 16 * ch];
#pragma unroll
        for (int jp = 0; jp < 8; jp++) {
            ull pv[8], ov[8];
#pragma unroll
            for (int m = 0; m < 8; m++)
                pv[m] = *(const ull*)(p1r + (16 * m) * SA + 2 * jp);
#pragma unroll
            for (int n = 0; n < 8; n++)
                ov[n] = *(const ull*)(p2r + (16 * n) * SA + 2 * jp);
#pragma unroll
            for (int m = 0; m < 8; m++)
#pragma unroll
                for (int n = 0; n < 8; n++) ffma2(acc[m][n], pv[m], ov[n]);
        }
    }

    // ---- phase 6: fused distance (A from gmem, L2-hot) + block reduce ----
    float dsum = 0.f;
#pragma unroll
    for (int m = 0; m < 8; m++)
#pragma unroll
        for (int n = 0; n < 8; n++) {
            float a = Ag[(ty + 16 * m) * WH + tx + 16 * n];
            float d = a - f2sum(acc[m][n]);
            dsum += d * d;
        }
    xch[tid] = dsum;
    __syncthreads();
    for (int st = 128; st > 0; st >>= 1) {
        if (tid < st) xch[tid] += xch[tid + st];
        __syncthreads();
    }
    if (tid == 0) g_dd[blk] = xch[0];
}

// ===========================================================================
// Kernel 5: final margin ranking loss
// ===========================================================================
__global__ void loss_kernel(float* __restrict__ out) {
    int tid = threadIdx.x;
    float s = 0.f;
    for (int b = tid; b < N_SAMP; b += 256) {
        float dap = sqrtf(g_dd[2 * b]);
        float dan = sqrtf(g_dd[2 * b + 1]);
        float v = dap - dan + 0.3f;
        s += (v > 0.f) ? v : 0.f;
    }
    __shared__ float red[256];
    red[tid] = s;
    __syncthreads();
    for (int st = 128; st > 0; st >>= 1) {
        if (tid < st) red[tid] += red[tid + st];
        __syncthreads();
    }
    if (tid == 0) out[0] = red[0] * (1.0f / (float)N_SAMP);
}

// ===========================================================================
extern "C" void kernel_launch(void* const* d_in, const int* in_sizes, int n_in,
                              void* d_out, int out_size) {
    const float* X;
    const int*   T;
    if (n_in >= 2 && in_sizes[0] == N_SAMP && in_sizes[1] != N_SAMP) {
        T = (const int*)d_in[0];
        X = (const float*)d_in[1];
    } else {
        X = (const float*)d_in[0];
        T = (const int*)d_in[1];
    }

    const int smem_attn = 2 * 128 * SA * (int)sizeof(float);  // 133120 B
    cudaFuncSetAttribute(attn_kernel, cudaFuncAttributeMaxDynamicSharedMemorySize,
                         smem_attn);

    gram_f2<<<144, 256>>>(X);
    gram_reduce<<<36, 256>>>();
    mine_kernel<<<N_SAMP, 256>>>(T);
    attn_kernel<<<2 * N_SAMP, 256, smem_attn>>>(X);
    loss_kernel<<<1, 256>>>((float*)d_out);
}